// round 9
// baseline (speedup 1.0000x reference)
#include <cuda_runtime.h>
#include <cstdint>

#define N_NODES 100000
#define N_EDGES 1600000
#define N_GRAPHS 512
#define N_REL 4
#define N_TYPES 13
#define HID 128
#define WCOLS 640            // logical K: [self(128) | rel0..3 (4*128)]
#define GCOLS 512            // stored aggregate cols (self removed)
#define BN_EPS 1e-5f
#define L2_EPS 1e-12f
#define NB_SCAN ((N_NODES + 255) / 256)   // 391
#define NCHUNK 4

// ---------------- device scratch ---------------------------------------------
__device__ __align__(16) float  g_hA[N_NODES * HID];           // layer-0 output (tf32 bits)
__device__ __align__(16) float  g_hB[N_NODES * HID];           // layer-1 GEMM output (pre-BN)
__device__ __align__(16) float  g_G[(size_t)N_NODES * GCOLS];  // per-rel aggregates (tf32 bits)
__device__ __align__(16) float  g_T0[N_TYPES * WCOLS];
__device__ __align__(16) float  g_W1[WCOLS * 128];             // tf32-truncated packed weights
__device__ int    g_ntype[N_NODES];
__device__ int    g_cnt4[N_NODES * 4];
__device__ float  g_winv[N_NODES * 4];
__device__ int    g_offs[N_NODES + 1];
__device__ int    g_cursor[N_NODES];
__device__ int    g_bsum[NB_SCAN];
__device__ int    g_bpre[NB_SCAN];
__device__ int    g_elist[N_EDGES];                            // packed (src<<2)|rel
__device__ double g_stats[512];   // [0:128) sum0 [128:256) sq0 [256:384) sum1 [384:512) sq1
__device__ __align__(16) float g_pool[N_GRAPHS * HID];
__device__ int    g_gcnt[N_GRAPHS];

// ---------------- prep: zero accumulators + node types ------------------------
__global__ void k_prep(const float* __restrict__ x) {
    int i = blockIdx.x * blockDim.x + threadIdx.x;
    if (i < N_NODES * 4) g_cnt4[i] = 0;
    if (i < 512) g_stats[i] = 0.0;
    if (i < N_GRAPHS * HID) g_pool[i] = 0.f;
    if (i < N_GRAPHS) g_gcnt[i] = 0;
    if (i < N_NODES) {
        const float* row = x + (size_t)i * N_TYPES;
        int t = 0; float best = row[0];
        #pragma unroll
        for (int q = 1; q < N_TYPES; q++) {
            float v = row[q];
            if (v > best) { best = v; t = q; }
        }
        g_ntype[i] = t;
    }
}

// ---------------- per-(dst,rel) in-degree counts ------------------------------
__global__ void k_count(const int* __restrict__ ei, const int* __restrict__ etype) {
    int e = blockIdx.x * blockDim.x + threadIdx.x;
    if (e >= N_EDGES) return;
    int dst = ei[N_EDGES + e];
    int et  = etype[e];
    atomicAdd(&g_cnt4[dst * 4 + et], 1);
}

// ---------------- parallel scan, phase 1: block-local (+ winv) ----------------
__global__ void k_scan1() {
    __shared__ int sh[256];
    int tid = threadIdx.x;
    int i = blockIdx.x * 256 + tid;
    int d = 0;
    if (i < N_NODES) {
        int c0 = g_cnt4[4*i+0], c1 = g_cnt4[4*i+1];
        int c2 = g_cnt4[4*i+2], c3 = g_cnt4[4*i+3];
        d = c0 + c1 + c2 + c3;
        g_winv[4*i+0] = 1.f / fmaxf((float)c0, 1.f);
        g_winv[4*i+1] = 1.f / fmaxf((float)c1, 1.f);
        g_winv[4*i+2] = 1.f / fmaxf((float)c2, 1.f);
        g_winv[4*i+3] = 1.f / fmaxf((float)c3, 1.f);
    }
    sh[tid] = d;
    __syncthreads();
    #pragma unroll
    for (int off = 1; off < 256; off <<= 1) {
        int t = (tid >= off) ? sh[tid - off] : 0;
        __syncthreads();
        sh[tid] += t;
        __syncthreads();
    }
    if (i < N_NODES) g_offs[i] = sh[tid] - d;          // block-local exclusive
    if (tid == 255) g_bsum[blockIdx.x] = sh[255];
}

// ---------------- phase 2: scan block sums (1 block) ---------------------------
__global__ void k_scan2() {
    __shared__ int sh[512];
    int tid = threadIdx.x;
    int v = (tid < NB_SCAN) ? g_bsum[tid] : 0;
    sh[tid] = v;
    __syncthreads();
    #pragma unroll
    for (int off = 1; off < 512; off <<= 1) {
        int t = (tid >= off) ? sh[tid - off] : 0;
        __syncthreads();
        sh[tid] += t;
        __syncthreads();
    }
    if (tid < NB_SCAN) g_bpre[tid] = sh[tid] - v;      // exclusive
}

// ---------------- phase 3: add base, emit cursor -------------------------------
__global__ void k_scan3() {
    int i = blockIdx.x * blockDim.x + threadIdx.x;
    if (i < N_NODES) {
        int o = g_offs[i] + g_bpre[i >> 8];
        g_offs[i] = o;
        g_cursor[i] = o;
    }
    if (i == 0) g_offs[N_NODES] = N_EDGES;
}

// ---------------- fill CSR edge list -------------------------------------------
__global__ void k_fill(const int* __restrict__ ei, const int* __restrict__ etype) {
    int e = blockIdx.x * blockDim.x + threadIdx.x;
    if (e >= N_EDGES) return;
    int src = ei[e];
    int dst = ei[N_EDGES + e];
    int et  = etype[e];
    int pos = atomicAdd(&g_cursor[dst], 1);
    g_elist[pos] = (src << 2) | et;
}

// ---------------- weights: layer-0 table + packed tf32 layer-1 weights ----------
__global__ void k_weights(const float* __restrict__ emb, const float* __restrict__ Wrel,
                          const float* __restrict__ Wroot, const float* __restrict__ bias) {
    int i = blockIdx.x * blockDim.x + threadIdx.x;
    if (i < N_TYPES * WCOLS) {
        int t = i / WCOLS, c = i % WCOLS;
        float s;
        if (c < 128) {
            s = bias[c];
            #pragma unroll 8
            for (int k = 0; k < 128; k++) s += emb[t*128 + k] * Wroot[k*128 + c];
        } else {
            int r = (c - 128) >> 7, j = (c - 128) & 127;
            const float* wr = Wrel + r * 16384;
            s = 0.f;
            #pragma unroll 8
            for (int k = 0; k < 128; k++) s += emb[t*128 + k] * wr[k*128 + j];
        }
        g_T0[i] = s;
    }
    int w = i - N_TYPES * WCOLS;
    if (w >= 0 && w < WCOLS * 128) {
        int kk = w / 128, c = w % 128;
        float v;
        if (kk < 128) v = Wroot[16384 + kk*128 + c];
        else {
            int r = (kk - 128) >> 7, k = (kk - 128) & 127;
            v = Wrel[(4 + r) * 16384 + k*128 + c];
        }
        uint32_t tb;
        asm("cvt.rna.tf32.f32 %0, %1;" : "=r"(tb) : "f"(v));
        g_W1[w] = __uint_as_float(tb);
    }
}

// ---------------- layer-0 aggregation: table lookup gather → g_hA (1 node/warp) -
__global__ __launch_bounds__(256) void k_agg0() {
    int node = (blockIdx.x * 256 + threadIdx.x) >> 5;
    int lane = threadIdx.x & 31;
    if (node >= N_NODES) return;
    float w0 = g_winv[node*4+0], w1 = g_winv[node*4+1];
    float w2 = g_winv[node*4+2], w3 = g_winv[node*4+3];
    float4 acc = *reinterpret_cast<const float4*>(&g_T0[g_ntype[node] * WCOLS + lane * 4]);
    int beg = g_offs[node], end = g_offs[node + 1];

    auto addw = [&](int et, float4 m) {
        float w = (et == 0) ? w0 : (et == 1) ? w1 : (et == 2) ? w2 : w3;
        acc.x += m.x * w; acc.y += m.y * w; acc.z += m.z * w; acc.w += m.w * w;
    };

    int e = beg;
    for (; e + 4 <= end; e += 4) {
        int p0 = g_elist[e], p1 = g_elist[e+1], p2 = g_elist[e+2], p3 = g_elist[e+3];
        int t0 = g_ntype[p0 >> 2], t1 = g_ntype[p1 >> 2];
        int t2 = g_ntype[p2 >> 2], t3 = g_ntype[p3 >> 2];
        float4 m0 = *reinterpret_cast<const float4*>(&g_T0[t0 * WCOLS + 128 + (p0 & 3) * 128 + lane * 4]);
        float4 m1 = *reinterpret_cast<const float4*>(&g_T0[t1 * WCOLS + 128 + (p1 & 3) * 128 + lane * 4]);
        float4 m2 = *reinterpret_cast<const float4*>(&g_T0[t2 * WCOLS + 128 + (p2 & 3) * 128 + lane * 4]);
        float4 m3 = *reinterpret_cast<const float4*>(&g_T0[t3 * WCOLS + 128 + (p3 & 3) * 128 + lane * 4]);
        addw(p0 & 3, m0); addw(p1 & 3, m1); addw(p2 & 3, m2); addw(p3 & 3, m3);
    }
    for (; e < end; e++) {
        int p = g_elist[e];
        int ts = g_ntype[p >> 2];
        float4 m = *reinterpret_cast<const float4*>(&g_T0[ts * WCOLS + 128 + (p & 3) * 128 + lane * 4]);
        addw(p & 3, m);
    }
    *reinterpret_cast<float4*>(&g_hA[(size_t)node * 128 + lane * 4]) = acc;
}

// ---------------- BN stats layer 0 (separate pass: 512 atomics/address) ---------
__global__ void k_bnstats0() {
    int col = threadIdx.x;             // 128 threads
    double s = 0.0, s2 = 0.0;
    for (int r = blockIdx.x; r < N_NODES; r += gridDim.x) {
        float v = g_hA[(size_t)r * 128 + col];
        s  += (double)v;
        s2 += (double)v * (double)v;
    }
    atomicAdd(&g_stats[col], s);
    atomicAdd(&g_stats[128 + col], s2);
}

// ---------------- BN apply + PReLU + L2norm, write tf32-truncated ---------------
__global__ __launch_bounds__(256) void k_bnapply0(const float* __restrict__ gamma,
                                                  const float* __restrict__ beta,
                                                  const float* __restrict__ pa) {
    int node = (blockIdx.x * 256 + threadIdx.x) >> 5;
    int lane = threadIdx.x & 31;
    if (node >= N_NODES) return;
    float alpha = pa[0];
    float4 v = *reinterpret_cast<const float4*>(&g_hA[(size_t)node * 128 + lane * 4]);
    float vin[4] = { v.x, v.y, v.z, v.w };
    float y[4]; float ss = 0.f;
    #pragma unroll
    for (int q = 0; q < 4; q++) {
        int c = lane * 4 + q;
        double mu  = g_stats[c] * (1.0 / N_NODES);
        double var = g_stats[128 + c] * (1.0 / N_NODES) - mu * mu;
        float sc = rsqrtf((float)var + BN_EPS) * gamma[c];
        float val = (vin[q] - (float)mu) * sc + beta[c];
        val = (val >= 0.f) ? val : alpha * val;
        y[q] = val;
        ss += val * val;
    }
    #pragma unroll
    for (int o = 16; o; o >>= 1) ss += __shfl_xor_sync(0xffffffffu, ss, o);
    float inv = 1.f / fmaxf(sqrtf(ss), L2_EPS);
    uint32_t t[4];
    #pragma unroll
    for (int q = 0; q < 4; q++) {
        float val = y[q] * inv;
        asm("cvt.rna.tf32.f32 %0, %1;" : "=r"(t[q]) : "f"(val));
    }
    float4 o4 = make_float4(__uint_as_float(t[0]), __uint_as_float(t[1]),
                            __uint_as_float(t[2]), __uint_as_float(t[3]));
    *reinterpret_cast<float4*>(&g_hA[(size_t)node * 128 + lane * 4]) = o4;
}

// ---------------- layer-1 pre-aggregation → g_G[N,512] (tf32, streaming stores) -
// chunked [node0, node_end) for cross-stream pipelining
__global__ __launch_bounds__(256) void k_gather1(int node0, int node_end) {
    int node = node0 + ((blockIdx.x * 256 + threadIdx.x) >> 5);
    int lane = threadIdx.x & 31;
    if (node >= node_end) return;
    float4 a0 = make_float4(0,0,0,0), a1 = a0, a2 = a0, a3 = a0;
    int beg = g_offs[node], end = g_offs[node + 1];

    auto addv = [&](int et, float4 v) {
        if (et == 0)      { a0.x += v.x; a0.y += v.y; a0.z += v.z; a0.w += v.w; }
        else if (et == 1) { a1.x += v.x; a1.y += v.y; a1.z += v.z; a1.w += v.w; }
        else if (et == 2) { a2.x += v.x; a2.y += v.y; a2.z += v.z; a2.w += v.w; }
        else              { a3.x += v.x; a3.y += v.y; a3.z += v.z; a3.w += v.w; }
    };

    int e = beg;
    for (; e + 4 <= end; e += 4) {
        int p0 = g_elist[e], p1 = g_elist[e+1], p2 = g_elist[e+2], p3 = g_elist[e+3];
        float4 v0 = *reinterpret_cast<const float4*>(&g_hA[(size_t)(p0 >> 2) * 128 + lane * 4]);
        float4 v1 = *reinterpret_cast<const float4*>(&g_hA[(size_t)(p1 >> 2) * 128 + lane * 4]);
        float4 v2 = *reinterpret_cast<const float4*>(&g_hA[(size_t)(p2 >> 2) * 128 + lane * 4]);
        float4 v3 = *reinterpret_cast<const float4*>(&g_hA[(size_t)(p3 >> 2) * 128 + lane * 4]);
        addv(p0 & 3, v0); addv(p1 & 3, v1); addv(p2 & 3, v2); addv(p3 & 3, v3);
    }
    for (; e < end; e++) {
        int p = g_elist[e];
        float4 v = *reinterpret_cast<const float4*>(&g_hA[(size_t)(p >> 2) * 128 + lane * 4]);
        addv(p & 3, v);
    }

    float w0 = g_winv[node*4+0], w1 = g_winv[node*4+1];
    float w2 = g_winv[node*4+2], w3 = g_winv[node*4+3];
    float vals[16] = { a0.x*w0, a0.y*w0, a0.z*w0, a0.w*w0,
                       a1.x*w1, a1.y*w1, a1.z*w1, a1.w*w1,
                       a2.x*w2, a2.y*w2, a2.z*w2, a2.w*w2,
                       a3.x*w3, a3.y*w3, a3.z*w3, a3.w*w3 };
    uint32_t tb[16];
    #pragma unroll
    for (int q = 0; q < 16; q++)
        asm("cvt.rna.tf32.f32 %0, %1;" : "=r"(tb[q]) : "f"(vals[q]));
    size_t base = (size_t)node * GCOLS + lane * 4;
    #pragma unroll
    for (int r = 0; r < 4; r++) {
        float4 o4 = make_float4(__uint_as_float(tb[r*4+0]), __uint_as_float(tb[r*4+1]),
                                __uint_as_float(tb[r*4+2]), __uint_as_float(tb[r*4+3]));
        __stcs(reinterpret_cast<float4*>(&g_G[base + (size_t)r * 128]), o4);  // evict-first
    }
}

// ---------------- cp.async helper (L2-only) -------------------------------------
__device__ __forceinline__ void cp16(void* smem_dst, const void* gsrc, int src_bytes) {
    unsigned sa = (unsigned)__cvta_generic_to_shared(smem_dst);
    asm volatile("cp.async.cg.shared.global [%0], [%1], 16, %2;"
                 :: "r"(sa), "l"(gsrc), "r"(src_bytes));
}

// ---------------- tf32 GEMM: g_hB[rows,128] = [hA|G] @ g_W1 + bias ---------------
// chunked [row_base, row_end) for cross-stream pipelining; fused BN stats.
__global__ __launch_bounds__(256, 2) void k_gemm_tf32(const float* __restrict__ bias,
                                                      int row_base, int row_end) {
    extern __shared__ float sm[];
    float (*As)[128][36]  = (float(*)[128][36])sm;                      // 2 stages
    float (*Bs)[32][136]  = (float(*)[32][136])(sm + 2*128*36);
    float* ssum = sm + 2*128*36 + 2*32*136;
    float* ssq  = ssum + 128;

    const int tid  = threadIdx.x;
    const int lane = tid & 31;
    const int warp = tid >> 5;
    const int row0 = row_base + blockIdx.x * 128;
    const int warpM = (warp & 3) * 32;
    const int warpN = (warp >> 2) * 64;
    const int lq = lane >> 2;   // 0..7
    const int lr = lane & 3;    // 0..3

    if (tid < 128) { ssum[tid] = 0.f; ssq[tid] = 0.f; }

    auto loadA = [&](int s, int kc) {
        #pragma unroll
        for (int i = 0; i < 4; i++) {
            int f = tid + i * 256;
            int r = f >> 3, c = (f & 7) * 4;
            int gr = row0 + r;
            bool valid = gr < row_end;
            const float* src;
            if (kc < 128) src = &g_hA[(size_t)(valid ? gr : 0) * 128 + kc + c];
            else          src = &g_G[(size_t)(valid ? gr : 0) * GCOLS + (kc - 128) + c];
            cp16(&As[s][r][c], src, valid ? 16 : 0);
        }
    };
    auto loadB = [&](int s, int kc) {
        #pragma unroll
        for (int i = 0; i < 4; i++) {
            int f = tid + i * 256;
            int r = f >> 5, c = (f & 31) * 4;
            cp16(&Bs[s][r][c], &g_W1[(kc + r) * 128 + c], 16);
        }
    };

    float acc[2][8][4];
    #pragma unroll
    for (int mt = 0; mt < 2; mt++)
        #pragma unroll
        for (int nt = 0; nt < 8; nt++)
            #pragma unroll
            for (int q = 0; q < 4; q++) acc[mt][nt][q] = 0.f;

    const int NT = WCOLS / 32;   // 20
    loadA(0, 0); loadB(0, 0);
    asm volatile("cp.async.commit_group;");

    for (int kt = 0; kt < NT; kt++) {
        if (kt + 1 < NT) {
            loadA((kt + 1) & 1, (kt + 1) * 32);
            loadB((kt + 1) & 1, (kt + 1) * 32);
            asm volatile("cp.async.commit_group;");
            asm volatile("cp.async.wait_group 1;");
        } else {
            asm volatile("cp.async.wait_group 0;");
        }
        __syncthreads();
        const int buf = kt & 1;

        #pragma unroll
        for (int ks = 0; ks < 4; ks++) {
            const int k0 = ks * 8;
            uint32_t bf0[8], bf1[8];
            #pragma unroll
            for (int nt = 0; nt < 8; nt++) {
                int nc = warpN + nt * 8 + lq;
                bf0[nt] = __float_as_uint(Bs[buf][k0 + lr][nc]);
                bf1[nt] = __float_as_uint(Bs[buf][k0 + 4 + lr][nc]);
            }
            #pragma unroll
            for (int mt = 0; mt < 2; mt++) {
                int mr = warpM + mt * 16 + lq;
                uint32_t a0 = __float_as_uint(As[buf][mr    ][k0 + lr    ]);
                uint32_t a1 = __float_as_uint(As[buf][mr + 8][k0 + lr    ]);
                uint32_t a2 = __float_as_uint(As[buf][mr    ][k0 + 4 + lr]);
                uint32_t a3 = __float_as_uint(As[buf][mr + 8][k0 + 4 + lr]);
                #pragma unroll
                for (int nt = 0; nt < 8; nt++) {
                    asm volatile(
                        "mma.sync.aligned.m16n8k8.row.col.f32.tf32.tf32.f32 "
                        "{%0,%1,%2,%3}, {%4,%5,%6,%7}, {%8,%9}, {%0,%1,%2,%3};"
                        : "+f"(acc[mt][nt][0]), "+f"(acc[mt][nt][1]),
                          "+f"(acc[mt][nt][2]), "+f"(acc[mt][nt][3])
                        : "r"(a0), "r"(a1), "r"(a2), "r"(a3),
                          "r"(bf0[nt]), "r"(bf1[nt]));
                }
            }
        }
        __syncthreads();
    }

    // ---- epilogue: bias + streaming store + per-column partial stats ----
    float cs[8][2], cq[8][2];
    #pragma unroll
    for (int nt = 0; nt < 8; nt++) { cs[nt][0]=0.f; cs[nt][1]=0.f; cq[nt][0]=0.f; cq[nt][1]=0.f; }

    #pragma unroll
    for (int mt = 0; mt < 2; mt++) {
        int r_lo = row0 + warpM + mt * 16 + lq;
        int r_hi = r_lo + 8;
        bool vlo = r_lo < row_end, vhi = r_hi < row_end;
        #pragma unroll
        for (int nt = 0; nt < 8; nt++) {
            int c = warpN + nt * 8 + lr * 2;
            float b0 = bias[c], b1 = bias[c + 1];
            float v0 = acc[mt][nt][0] + b0, v1 = acc[mt][nt][1] + b1;
            float v2 = acc[mt][nt][2] + b0, v3 = acc[mt][nt][3] + b1;
            if (vlo) {
                __stcs(reinterpret_cast<float2*>(&g_hB[(size_t)r_lo * 128 + c]), make_float2(v0, v1));
                cs[nt][0] += v0; cq[nt][0] += v0 * v0;
                cs[nt][1] += v1; cq[nt][1] += v1 * v1;
            }
            if (vhi) {
                __stcs(reinterpret_cast<float2*>(&g_hB[(size_t)r_hi * 128 + c]), make_float2(v2, v3));
                cs[nt][0] += v2; cq[nt][0] += v2 * v2;
                cs[nt][1] += v3; cq[nt][1] += v3 * v3;
            }
        }
    }
    #pragma unroll
    for (int nt = 0; nt < 8; nt++)
        #pragma unroll
        for (int p = 0; p < 2; p++) {
            #pragma unroll
            for (int off = 4; off < 32; off <<= 1) {
                cs[nt][p] += __shfl_xor_sync(0xffffffffu, cs[nt][p], off);
                cq[nt][p] += __shfl_xor_sync(0xffffffffu, cq[nt][p], off);
            }
        }
    if (lq == 0) {
        #pragma unroll
        for (int nt = 0; nt < 8; nt++)
            #pragma unroll
            for (int p = 0; p < 2; p++) {
                int c = warpN + nt * 8 + lr * 2 + p;
                atomicAdd(&ssum[c], cs[nt][p]);
                atomicAdd(&ssq[c],  cq[nt][p]);
            }
    }
    __syncthreads();
    if (tid < 128)       atomicAdd(&g_stats[256 + tid], (double)ssum[tid]);
    else                 atomicAdd(&g_stats[384 + tid - 128], (double)ssq[tid - 128]);
}

// ---------------- fused BN+PReLU+L2norm+mean-pool (sorted batch) ----------------
__global__ __launch_bounds__(256) void k_bnpool(const int* __restrict__ batch,
                                                const float* __restrict__ gamma,
                                                const float* __restrict__ beta,
                                                const float* __restrict__ pa) {
    const int NPW = 16;
    int warpg = (blockIdx.x * 256 + threadIdx.x) >> 5;
    int lane  = threadIdx.x & 31;
    int n0 = warpg * NPW;
    if (n0 >= N_NODES) return;
    int n1 = min(n0 + NPW, N_NODES);
    float alpha = pa[1];

    float mu[4], sc[4], bt[4];
    #pragma unroll
    for (int q = 0; q < 4; q++) {
        int c = lane * 4 + q;
        double m  = g_stats[256 + c] * (1.0 / N_NODES);
        double vv = g_stats[384 + c] * (1.0 / N_NODES) - m * m;
        mu[q] = (float)m;
        sc[q] = rsqrtf((float)vv + BN_EPS) * gamma[c];
        bt[q] = beta[c];
    }

    float acc[4] = {0.f, 0.f, 0.f, 0.f};
    int cur = -1, cnt = 0;
    for (int n = n0; n < n1; n++) {
        float4 v = __ldcs(reinterpret_cast<const float4*>(&g_hB[(size_t)n * 128 + lane * 4]));
        float y[4] = { v.x, v.y, v.z, v.w };
        float ss = 0.f;
        #pragma unroll
        for (int q = 0; q < 4; q++) {
            float val = (y[q] - mu[q]) * sc[q] + bt[q];
            val = (val >= 0.f) ? val : alpha * val;
            y[q] = val;
            ss += val * val;
        }
        #pragma unroll
        for (int o = 16; o; o >>= 1) ss += __shfl_xor_sync(0xffffffffu, ss, o);
        float inv = 1.f / fmaxf(sqrtf(ss), L2_EPS);
        int g = batch[n];
        if (g != cur) {
            if (cur >= 0) {
                #pragma unroll
                for (int q = 0; q < 4; q++) atomicAdd(&g_pool[cur * 128 + lane * 4 + q], acc[q]);
                if (lane == 0) atomicAdd(&g_gcnt[cur], cnt);
            }
            cur = g; cnt = 1;
            #pragma unroll
            for (int q = 0; q < 4; q++) acc[q] = y[q] * inv;
        } else {
            cnt++;
            #pragma unroll
            for (int q = 0; q < 4; q++) acc[q] += y[q] * inv;
        }
    }
    if (cur >= 0) {
        #pragma unroll
        for (int q = 0; q < 4; q++) atomicAdd(&g_pool[cur * 128 + lane * 4 + q], acc[q]);
        if (lane == 0) atomicAdd(&g_gcnt[cur], cnt);
    }
}

// ---------------- MLP head: one block per graph ---------------------------------
__global__ __launch_bounds__(256) void k_mlp(const float* __restrict__ fc1w, const float* __restrict__ fc1b,
                                             const float* __restrict__ fc2w, const float* __restrict__ fc2b,
                                             const float* __restrict__ ow,  const float* __restrict__ ob,
                                             float* __restrict__ out) {
    int g = blockIdx.x;
    int t = threadIdx.x;
    __shared__ float sg[128], s1[256], s2[128], red[256];
    float invc = 1.f / fmaxf((float)g_gcnt[g], 1.f);
    if (t < 128) sg[t] = g_pool[g * 128 + t] * invc;
    __syncthreads();
    float s = fc1b[t];
    #pragma unroll 8
    for (int k = 0; k < 128; k++) s += sg[k] * fc1w[k * 256 + t];
    s1[t] = fmaxf(s, 0.f);
    __syncthreads();
    if (t < 128) {
        float s2v = fc2b[t];
        #pragma unroll 8
        for (int k = 0; k < 256; k++) s2v += s1[k] * fc2w[k * 128 + t];
        s2[t] = fmaxf(s2v, 0.f);
    }
    __syncthreads();
    red[t] = (t < 128) ? s2[t] * ow[t] : 0.f;
    __syncthreads();
    for (int o = 128; o > 0; o >>= 1) {
        if (t < o) red[t] += red[t + o];
        __syncthreads();
    }
    if (t == 0) out[g] = red[0] + ob[0];
}

// =============================================================================
extern "C" void kernel_launch(void* const* d_in, const int* in_sizes, int n_in,
                              void* d_out, int out_size) {
    const float* x      = (const float*)d_in[0];
    const int*   ei     = (const int*)  d_in[1];
    const int*   etype  = (const int*)  d_in[2];
    const int*   batch  = (const int*)  d_in[3];
    const float* emb    = (const float*)d_in[4];
    const float* Wrel   = (const float*)d_in[5];
    const float* Wroot  = (const float*)d_in[6];
    const float* cbias  = (const float*)d_in[7];
    const float* gamma  = (const float*)d_in[8];
    const float* beta   = (const float*)d_in[9];
    const float* pa     = (const float*)d_in[10];
    const float* fc1w   = (const float*)d_in[11];
    const float* fc1b   = (const float*)d_in[12];
    const float* fc2w   = (const float*)d_in[13];
    const float* fc2b   = (const float*)d_in[14];
    const float* ow     = (const float*)d_in[15];
    const float* ob     = (const float*)d_in[16];
    float* out = (float*)d_out;

    const int TB = 256;
    const int GEMM_SMEM = (2*128*36 + 2*32*136 + 256) * sizeof(float);

    static cudaStream_t s1 = nullptr;
    static cudaEvent_t evStart, evW, evG[NCHUNK], evDone;
    if (!s1) {
        cudaFuncSetAttribute(k_gemm_tf32, cudaFuncAttributeMaxDynamicSharedMemorySize, GEMM_SMEM);
        cudaStreamCreateWithFlags(&s1, cudaStreamNonBlocking);
        cudaEventCreateWithFlags(&evStart, cudaEventDisableTiming);
        cudaEventCreateWithFlags(&evW, cudaEventDisableTiming);
        for (int c = 0; c < NCHUNK; c++)
            cudaEventCreateWithFlags(&evG[c], cudaEventDisableTiming);
        cudaEventCreateWithFlags(&evDone, cudaEventDisableTiming);
    }

    // ---- fork: weights on s1 (independent of graph structure) ----
    cudaEventRecord(evStart, 0);
    cudaStreamWaitEvent(s1, evStart, 0);
    k_weights<<<(N_TYPES * WCOLS + WCOLS * 128 + TB - 1) / TB, TB, 0, s1>>>(emb, Wrel, Wroot, cbias);
    cudaEventRecord(evW, s1);

    // ---- prep + graph structure (default stream) ----
    k_prep<<<(N_NODES * 4 + TB - 1) / TB, TB>>>(x);
    k_count<<<(N_EDGES + TB - 1) / TB, TB>>>(ei, etype);
    k_scan1<<<NB_SCAN, 256>>>();
    k_scan2<<<1, 512>>>();
    k_scan3<<<(N_NODES + TB - 1) / TB, TB>>>();
    k_fill<<<(N_EDGES + TB - 1) / TB, TB>>>(ei, etype);

    // join weights before layer 0 (agg0 needs g_T0)
    cudaStreamWaitEvent(0, evW, 0);

    const int nodeWarpBlocks = (N_NODES * 32 + TB - 1) / TB;
    const int npwBlocks = ((N_NODES + 15) / 16 * 32 + TB - 1) / TB;

    // ---- layer 0 (table shortcut) ----
    k_agg0<<<nodeWarpBlocks, TB>>>();
    k_bnstats0<<<512, 128>>>();
    k_bnapply0<<<nodeWarpBlocks, TB>>>(gamma, beta, pa);

    // ---- layer 1: gather (default) pipelined with GEMM (s1) over 4 chunks ----
    const int CH = 25088;   // 128-aligned chunk
    for (int c = 0; c < NCHUNK; c++) {
        int start = c * CH;
        int end   = (c == NCHUNK - 1) ? N_NODES : (c + 1) * CH;
        int nodes = end - start;
        int gblocks = (nodes * 32 + TB - 1) / TB;
        k_gather1<<<gblocks, TB>>>(start, end);
        cudaEventRecord(evG[c], 0);
        cudaStreamWaitEvent(s1, evG[c], 0);
        int mblocks = (nodes + 127) / 128;
        k_gemm_tf32<<<mblocks, 256, GEMM_SMEM, s1>>>(cbias + 128, start, end);
    }
    cudaEventRecord(evDone, s1);
    cudaStreamWaitEvent(0, evDone, 0);

    // ---- fused BN+PReLU+L2norm+pool, then MLP ----
    k_bnpool<<<npwBlocks, TB>>>(batch, gamma + 128, beta + 128, pa);
    k_mlp<<<N_GRAPHS, 256>>>(fc1w, fc1b, fc2w, fc2b, ow, ob, out);
}

// round 10
// speedup vs baseline: 1.0593x; 1.0593x over previous
#include <cuda_runtime.h>
#include <cstdint>

#define N_NODES 100000
#define N_EDGES 1600000
#define N_GRAPHS 512
#define N_REL 4
#define N_TYPES 13
#define HID 128
#define WCOLS 640            // logical K: [self(128) | rel0..3 (4*128)]
#define GCOLS 512            // stored aggregate cols (self removed)
#define BN_EPS 1e-5f
#define L2_EPS 1e-12f
#define NB_SCAN ((N_NODES + 255) / 256)   // 391

// ---------------- device scratch ---------------------------------------------
__device__ __align__(16) float  g_hA[N_NODES * HID];           // layer-0 output (tf32 bits)
__device__ __align__(16) float  g_hB[N_NODES * HID];           // layer-1 GEMM output (pre-BN)
__device__ __align__(16) float  g_G[(size_t)N_NODES * GCOLS];  // per-rel aggregates (tf32 bits)
__device__ __align__(16) float  g_T0[N_TYPES * WCOLS];
__device__ __align__(16) float  g_W1[WCOLS * 128];             // tf32-truncated packed weights
__device__ int    g_ntype[N_NODES];
__device__ int    g_cnt4[N_NODES * 4];
__device__ float  g_winv[N_NODES * 4];
__device__ int    g_offs[N_NODES + 1];
__device__ int    g_cursor[N_NODES];
__device__ int    g_bsum[NB_SCAN];
__device__ int    g_bpre[NB_SCAN];
__device__ int    g_elist[N_EDGES];                            // packed (src<<6)|(ts<<2)|et
__device__ double g_stats[512];   // [0:128) sum0 [128:256) sq0 [256:384) sum1 [384:512) sq1
__device__ __align__(16) float g_pool[N_GRAPHS * HID];
__device__ int    g_gcnt[N_GRAPHS];

// ---------------- prep: zero accumulators + node types ------------------------
__global__ void k_prep(const float* __restrict__ x) {
    int i = blockIdx.x * blockDim.x + threadIdx.x;
    if (i < N_NODES * 4) g_cnt4[i] = 0;
    if (i < 512) g_stats[i] = 0.0;
    if (i < N_GRAPHS * HID) g_pool[i] = 0.f;
    if (i < N_GRAPHS) g_gcnt[i] = 0;
    if (i < N_NODES) {
        const float* row = x + (size_t)i * N_TYPES;
        int t = 0; float best = row[0];
        #pragma unroll
        for (int q = 1; q < N_TYPES; q++) {
            float v = row[q];
            if (v > best) { best = v; t = q; }
        }
        g_ntype[i] = t;
    }
}

// ---------------- per-(dst,rel) in-degree counts ------------------------------
__global__ void k_count(const int* __restrict__ ei, const int* __restrict__ etype) {
    int e = blockIdx.x * blockDim.x + threadIdx.x;
    if (e >= N_EDGES) return;
    int dst = ei[N_EDGES + e];
    int et  = etype[e];
    atomicAdd(&g_cnt4[dst * 4 + et], 1);
}

// ---------------- parallel scan, phase 1: block-local (+ winv) ----------------
__global__ void k_scan1() {
    __shared__ int sh[256];
    int tid = threadIdx.x;
    int i = blockIdx.x * 256 + tid;
    int d = 0;
    if (i < N_NODES) {
        int c0 = g_cnt4[4*i+0], c1 = g_cnt4[4*i+1];
        int c2 = g_cnt4[4*i+2], c3 = g_cnt4[4*i+3];
        d = c0 + c1 + c2 + c3;
        g_winv[4*i+0] = 1.f / fmaxf((float)c0, 1.f);
        g_winv[4*i+1] = 1.f / fmaxf((float)c1, 1.f);
        g_winv[4*i+2] = 1.f / fmaxf((float)c2, 1.f);
        g_winv[4*i+3] = 1.f / fmaxf((float)c3, 1.f);
    }
    sh[tid] = d;
    __syncthreads();
    #pragma unroll
    for (int off = 1; off < 256; off <<= 1) {
        int t = (tid >= off) ? sh[tid - off] : 0;
        __syncthreads();
        sh[tid] += t;
        __syncthreads();
    }
    if (i < N_NODES) g_offs[i] = sh[tid] - d;          // block-local exclusive
    if (tid == 255) g_bsum[blockIdx.x] = sh[255];
}

// ---------------- phase 2: scan block sums (1 block) ---------------------------
__global__ void k_scan2() {
    __shared__ int sh[512];
    int tid = threadIdx.x;
    int v = (tid < NB_SCAN) ? g_bsum[tid] : 0;
    sh[tid] = v;
    __syncthreads();
    #pragma unroll
    for (int off = 1; off < 512; off <<= 1) {
        int t = (tid >= off) ? sh[tid - off] : 0;
        __syncthreads();
        sh[tid] += t;
        __syncthreads();
    }
    if (tid < NB_SCAN) g_bpre[tid] = sh[tid] - v;      // exclusive
}

// ---------------- phase 3: add base, emit cursor -------------------------------
__global__ void k_scan3() {
    int i = blockIdx.x * blockDim.x + threadIdx.x;
    if (i < N_NODES) {
        int o = g_offs[i] + g_bpre[i >> 8];
        g_offs[i] = o;
        g_cursor[i] = o;
    }
    if (i == 0) g_offs[N_NODES] = N_EDGES;
}

// ---------------- fill CSR edge list (packs src type: fill hides the random read)
__global__ void k_fill(const int* __restrict__ ei, const int* __restrict__ etype) {
    int e = blockIdx.x * blockDim.x + threadIdx.x;
    if (e >= N_EDGES) return;
    int src = ei[e];
    int dst = ei[N_EDGES + e];
    int et  = etype[e];
    int ts  = g_ntype[src];                    // random read, hidden under atomic latency
    int pos = atomicAdd(&g_cursor[dst], 1);
    g_elist[pos] = (src << 6) | (ts << 2) | et;
}

// ---------------- weights: layer-0 table + packed tf32 layer-1 weights ----------
__global__ void k_weights(const float* __restrict__ emb, const float* __restrict__ Wrel,
                          const float* __restrict__ Wroot, const float* __restrict__ bias) {
    int i = blockIdx.x * blockDim.x + threadIdx.x;
    if (i < N_TYPES * WCOLS) {
        int t = i / WCOLS, c = i % WCOLS;
        float s;
        if (c < 128) {
            s = bias[c];
            #pragma unroll 8
            for (int k = 0; k < 128; k++) s += emb[t*128 + k] * Wroot[k*128 + c];
        } else {
            int r = (c - 128) >> 7, j = (c - 128) & 127;
            const float* wr = Wrel + r * 16384;
            s = 0.f;
            #pragma unroll 8
            for (int k = 0; k < 128; k++) s += emb[t*128 + k] * wr[k*128 + j];
        }
        g_T0[i] = s;
    }
    int w = i - N_TYPES * WCOLS;
    if (w >= 0 && w < WCOLS * 128) {
        int kk = w / 128, c = w % 128;
        float v;
        if (kk < 128) v = Wroot[16384 + kk*128 + c];
        else {
            int r = (kk - 128) >> 7, k = (kk - 128) & 127;
            v = Wrel[(4 + r) * 16384 + k*128 + c];
        }
        uint32_t tb;
        asm("cvt.rna.tf32.f32 %0, %1;" : "=r"(tb) : "f"(v));
        g_W1[w] = __uint_as_float(tb);
    }
}

// ---------------- layer-0 aggregation: pure elist stream + L1 table lookups -----
__global__ __launch_bounds__(256) void k_agg0() {
    int node = (blockIdx.x * 256 + threadIdx.x) >> 5;
    int lane = threadIdx.x & 31;
    if (node >= N_NODES) return;
    float w0 = g_winv[node*4+0], w1 = g_winv[node*4+1];
    float w2 = g_winv[node*4+2], w3 = g_winv[node*4+3];
    float4 acc = *reinterpret_cast<const float4*>(&g_T0[g_ntype[node] * WCOLS + lane * 4]);
    int beg = g_offs[node], end = g_offs[node + 1];

    auto addw = [&](int et, float4 m) {
        float w = (et == 0) ? w0 : (et == 1) ? w1 : (et == 2) ? w2 : w3;
        acc.x += m.x * w; acc.y += m.y * w; acc.z += m.z * w; acc.w += m.w * w;
    };
    auto t0row = [&](int p) -> const float4* {
        int ts = (p >> 2) & 15, et = p & 3;
        return reinterpret_cast<const float4*>(&g_T0[ts * WCOLS + 128 + et * 128 + lane * 4]);
    };

    int e = beg;
    for (; e + 4 <= end; e += 4) {
        int p0 = g_elist[e], p1 = g_elist[e+1], p2 = g_elist[e+2], p3 = g_elist[e+3];
        float4 m0 = *t0row(p0);
        float4 m1 = *t0row(p1);
        float4 m2 = *t0row(p2);
        float4 m3 = *t0row(p3);
        addw(p0 & 3, m0); addw(p1 & 3, m1); addw(p2 & 3, m2); addw(p3 & 3, m3);
    }
    for (; e < end; e++) {
        int p = g_elist[e];
        float4 m = *t0row(p);
        addw(p & 3, m);
    }
    *reinterpret_cast<float4*>(&g_hA[(size_t)node * 128 + lane * 4]) = acc;
}

// ---------------- BN stats layer 0 (separate pass: 512 atomics/address) ---------
__global__ void k_bnstats0() {
    int col = threadIdx.x;             // 128 threads
    double s = 0.0, s2 = 0.0;
    for (int r = blockIdx.x; r < N_NODES; r += gridDim.x) {
        float v = g_hA[(size_t)r * 128 + col];
        s  += (double)v;
        s2 += (double)v * (double)v;
    }
    atomicAdd(&g_stats[col], s);
    atomicAdd(&g_stats[128 + col], s2);
}

// ---------------- BN apply + PReLU + L2norm, write tf32-truncated ---------------
__global__ __launch_bounds__(256) void k_bnapply0(const float* __restrict__ gamma,
                                                  const float* __restrict__ beta,
                                                  const float* __restrict__ pa) {
    int node = (blockIdx.x * 256 + threadIdx.x) >> 5;
    int lane = threadIdx.x & 31;
    if (node >= N_NODES) return;
    float alpha = pa[0];
    float4 v = *reinterpret_cast<const float4*>(&g_hA[(size_t)node * 128 + lane * 4]);
    float vin[4] = { v.x, v.y, v.z, v.w };
    float y[4]; float ss = 0.f;
    #pragma unroll
    for (int q = 0; q < 4; q++) {
        int c = lane * 4 + q;
        double mu  = g_stats[c] * (1.0 / N_NODES);
        double var = g_stats[128 + c] * (1.0 / N_NODES) - mu * mu;
        float sc = rsqrtf((float)var + BN_EPS) * gamma[c];
        float val = (vin[q] - (float)mu) * sc + beta[c];
        val = (val >= 0.f) ? val : alpha * val;
        y[q] = val;
        ss += val * val;
    }
    #pragma unroll
    for (int o = 16; o; o >>= 1) ss += __shfl_xor_sync(0xffffffffu, ss, o);
    float inv = 1.f / fmaxf(sqrtf(ss), L2_EPS);
    uint32_t t[4];
    #pragma unroll
    for (int q = 0; q < 4; q++) {
        float val = y[q] * inv;
        asm("cvt.rna.tf32.f32 %0, %1;" : "=r"(t[q]) : "f"(val));
    }
    float4 o4 = make_float4(__uint_as_float(t[0]), __uint_as_float(t[1]),
                            __uint_as_float(t[2]), __uint_as_float(t[3]));
    *reinterpret_cast<float4*>(&g_hA[(size_t)node * 128 + lane * 4]) = o4;
}

// ---------------- layer-1 pre-aggregation → g_G[N,512] (tf32, streaming stores) -
__global__ __launch_bounds__(256) void k_gather1() {
    int node = (blockIdx.x * 256 + threadIdx.x) >> 5;
    int lane = threadIdx.x & 31;
    if (node >= N_NODES) return;
    float4 a0 = make_float4(0,0,0,0), a1 = a0, a2 = a0, a3 = a0;
    int beg = g_offs[node], end = g_offs[node + 1];

    auto addv = [&](int et, float4 v) {
        if (et == 0)      { a0.x += v.x; a0.y += v.y; a0.z += v.z; a0.w += v.w; }
        else if (et == 1) { a1.x += v.x; a1.y += v.y; a1.z += v.z; a1.w += v.w; }
        else if (et == 2) { a2.x += v.x; a2.y += v.y; a2.z += v.z; a2.w += v.w; }
        else              { a3.x += v.x; a3.y += v.y; a3.z += v.z; a3.w += v.w; }
    };

    int e = beg;
    for (; e + 4 <= end; e += 4) {
        int p0 = g_elist[e], p1 = g_elist[e+1], p2 = g_elist[e+2], p3 = g_elist[e+3];
        float4 v0 = *reinterpret_cast<const float4*>(&g_hA[(size_t)(p0 >> 6) * 128 + lane * 4]);
        float4 v1 = *reinterpret_cast<const float4*>(&g_hA[(size_t)(p1 >> 6) * 128 + lane * 4]);
        float4 v2 = *reinterpret_cast<const float4*>(&g_hA[(size_t)(p2 >> 6) * 128 + lane * 4]);
        float4 v3 = *reinterpret_cast<const float4*>(&g_hA[(size_t)(p3 >> 6) * 128 + lane * 4]);
        addv(p0 & 3, v0); addv(p1 & 3, v1); addv(p2 & 3, v2); addv(p3 & 3, v3);
    }
    for (; e < end; e++) {
        int p = g_elist[e];
        float4 v = *reinterpret_cast<const float4*>(&g_hA[(size_t)(p >> 6) * 128 + lane * 4]);
        addv(p & 3, v);
    }

    float w0 = g_winv[node*4+0], w1 = g_winv[node*4+1];
    float w2 = g_winv[node*4+2], w3 = g_winv[node*4+3];
    float vals[16] = { a0.x*w0, a0.y*w0, a0.z*w0, a0.w*w0,
                       a1.x*w1, a1.y*w1, a1.z*w1, a1.w*w1,
                       a2.x*w2, a2.y*w2, a2.z*w2, a2.w*w2,
                       a3.x*w3, a3.y*w3, a3.z*w3, a3.w*w3 };
    uint32_t tb[16];
    #pragma unroll
    for (int q = 0; q < 16; q++)
        asm("cvt.rna.tf32.f32 %0, %1;" : "=r"(tb[q]) : "f"(vals[q]));
    size_t base = (size_t)node * GCOLS + lane * 4;
    #pragma unroll
    for (int r = 0; r < 4; r++) {
        float4 o4 = make_float4(__uint_as_float(tb[r*4+0]), __uint_as_float(tb[r*4+1]),
                                __uint_as_float(tb[r*4+2]), __uint_as_float(tb[r*4+3]));
        __stcs(reinterpret_cast<float4*>(&g_G[base + (size_t)r * 128]), o4);  // evict-first
    }
}

// ---------------- cp.async helper (L2-only) -------------------------------------
__device__ __forceinline__ void cp16(void* smem_dst, const void* gsrc, int src_bytes) {
    unsigned sa = (unsigned)__cvta_generic_to_shared(smem_dst);
    asm volatile("cp.async.cg.shared.global [%0], [%1], 16, %2;"
                 :: "r"(sa), "l"(gsrc), "r"(src_bytes));
}

// ---------------- tf32 GEMM: g_hB[N,128] = [hA|G][N,640] @ g_W1 + bias ----------
// 128x128 tile, BK=32, double-buffered cp.async, fused BN stats (layer 1).
__global__ __launch_bounds__(256, 2) void k_gemm_tf32(const float* __restrict__ bias) {
    extern __shared__ float sm[];
    float (*As)[128][36]  = (float(*)[128][36])sm;                      // 2 stages
    float (*Bs)[32][136]  = (float(*)[32][136])(sm + 2*128*36);
    float* ssum = sm + 2*128*36 + 2*32*136;
    float* ssq  = ssum + 128;

    const int tid  = threadIdx.x;
    const int lane = tid & 31;
    const int warp = tid >> 5;
    const int row0 = blockIdx.x * 128;
    const int warpM = (warp & 3) * 32;
    const int warpN = (warp >> 2) * 64;
    const int lq = lane >> 2;   // 0..7
    const int lr = lane & 3;    // 0..3

    if (tid < 128) { ssum[tid] = 0.f; ssq[tid] = 0.f; }

    auto loadA = [&](int s, int kc) {
        #pragma unroll
        for (int i = 0; i < 4; i++) {
            int f = tid + i * 256;
            int r = f >> 3, c = (f & 7) * 4;
            int gr = row0 + r;
            bool valid = gr < N_NODES;
            const float* src;
            if (kc < 128) src = &g_hA[(size_t)(valid ? gr : 0) * 128 + kc + c];
            else          src = &g_G[(size_t)(valid ? gr : 0) * GCOLS + (kc - 128) + c];
            cp16(&As[s][r][c], src, valid ? 16 : 0);
        }
    };
    auto loadB = [&](int s, int kc) {
        #pragma unroll
        for (int i = 0; i < 4; i++) {
            int f = tid + i * 256;
            int r = f >> 5, c = (f & 31) * 4;
            cp16(&Bs[s][r][c], &g_W1[(kc + r) * 128 + c], 16);
        }
    };

    float acc[2][8][4];
    #pragma unroll
    for (int mt = 0; mt < 2; mt++)
        #pragma unroll
        for (int nt = 0; nt < 8; nt++)
            #pragma unroll
            for (int q = 0; q < 4; q++) acc[mt][nt][q] = 0.f;

    const int NT = WCOLS / 32;   // 20
    loadA(0, 0); loadB(0, 0);
    asm volatile("cp.async.commit_group;");

    for (int kt = 0; kt < NT; kt++) {
        if (kt + 1 < NT) {
            loadA((kt + 1) & 1, (kt + 1) * 32);
            loadB((kt + 1) & 1, (kt + 1) * 32);
            asm volatile("cp.async.commit_group;");
            asm volatile("cp.async.wait_group 1;");
        } else {
            asm volatile("cp.async.wait_group 0;");
        }
        __syncthreads();
        const int buf = kt & 1;

        #pragma unroll
        for (int ks = 0; ks < 4; ks++) {
            const int k0 = ks * 8;
            uint32_t bf0[8], bf1[8];
            #pragma unroll
            for (int nt = 0; nt < 8; nt++) {
                int nc = warpN + nt * 8 + lq;
                bf0[nt] = __float_as_uint(Bs[buf][k0 + lr][nc]);
                bf1[nt] = __float_as_uint(Bs[buf][k0 + 4 + lr][nc]);
            }
            #pragma unroll
            for (int mt = 0; mt < 2; mt++) {
                int mr = warpM + mt * 16 + lq;
                uint32_t a0 = __float_as_uint(As[buf][mr    ][k0 + lr    ]);
                uint32_t a1 = __float_as_uint(As[buf][mr + 8][k0 + lr    ]);
                uint32_t a2 = __float_as_uint(As[buf][mr    ][k0 + 4 + lr]);
                uint32_t a3 = __float_as_uint(As[buf][mr + 8][k0 + 4 + lr]);
                #pragma unroll
                for (int nt = 0; nt < 8; nt++) {
                    asm volatile(
                        "mma.sync.aligned.m16n8k8.row.col.f32.tf32.tf32.f32 "
                        "{%0,%1,%2,%3}, {%4,%5,%6,%7}, {%8,%9}, {%0,%1,%2,%3};"
                        : "+f"(acc[mt][nt][0]), "+f"(acc[mt][nt][1]),
                          "+f"(acc[mt][nt][2]), "+f"(acc[mt][nt][3])
                        : "r"(a0), "r"(a1), "r"(a2), "r"(a3),
                          "r"(bf0[nt]), "r"(bf1[nt]));
                }
            }
        }
        __syncthreads();
    }

    // ---- epilogue: bias + streaming store + per-column partial stats ----
    float cs[8][2], cq[8][2];
    #pragma unroll
    for (int nt = 0; nt < 8; nt++) { cs[nt][0]=0.f; cs[nt][1]=0.f; cq[nt][0]=0.f; cq[nt][1]=0.f; }

    #pragma unroll
    for (int mt = 0; mt < 2; mt++) {
        int r_lo = row0 + warpM + mt * 16 + lq;
        int r_hi = r_lo + 8;
        bool vlo = r_lo < N_NODES, vhi = r_hi < N_NODES;
        #pragma unroll
        for (int nt = 0; nt < 8; nt++) {
            int c = warpN + nt * 8 + lr * 2;
            float b0 = bias[c], b1 = bias[c + 1];
            float v0 = acc[mt][nt][0] + b0, v1 = acc[mt][nt][1] + b1;
            float v2 = acc[mt][nt][2] + b0, v3 = acc[mt][nt][3] + b1;
            if (vlo) {
                __stcs(reinterpret_cast<float2*>(&g_hB[(size_t)r_lo * 128 + c]), make_float2(v0, v1));
                cs[nt][0] += v0; cq[nt][0] += v0 * v0;
                cs[nt][1] += v1; cq[nt][1] += v1 * v1;
            }
            if (vhi) {
                __stcs(reinterpret_cast<float2*>(&g_hB[(size_t)r_hi * 128 + c]), make_float2(v2, v3));
                cs[nt][0] += v2; cq[nt][0] += v2 * v2;
                cs[nt][1] += v3; cq[nt][1] += v3 * v3;
            }
        }
    }
    #pragma unroll
    for (int nt = 0; nt < 8; nt++)
        #pragma unroll
        for (int p = 0; p < 2; p++) {
            #pragma unroll
            for (int off = 4; off < 32; off <<= 1) {
                cs[nt][p] += __shfl_xor_sync(0xffffffffu, cs[nt][p], off);
                cq[nt][p] += __shfl_xor_sync(0xffffffffu, cq[nt][p], off);
            }
        }
    if (lq == 0) {
        #pragma unroll
        for (int nt = 0; nt < 8; nt++)
            #pragma unroll
            for (int p = 0; p < 2; p++) {
                int c = warpN + nt * 8 + lr * 2 + p;
                atomicAdd(&ssum[c], cs[nt][p]);
                atomicAdd(&ssq[c],  cq[nt][p]);
            }
    }
    __syncthreads();
    if (tid < 128)       atomicAdd(&g_stats[256 + tid], (double)ssum[tid]);
    else                 atomicAdd(&g_stats[384 + tid - 128], (double)ssq[tid - 128]);
}

// ---------------- fused BN+PReLU+L2norm+mean-pool (sorted batch) ----------------
__global__ __launch_bounds__(256) void k_bnpool(const int* __restrict__ batch,
                                                const float* __restrict__ gamma,
                                                const float* __restrict__ beta,
                                                const float* __restrict__ pa) {
    const int NPW = 16;
    int warpg = (blockIdx.x * 256 + threadIdx.x) >> 5;
    int lane  = threadIdx.x & 31;
    int n0 = warpg * NPW;
    if (n0 >= N_NODES) return;
    int n1 = min(n0 + NPW, N_NODES);
    float alpha = pa[1];

    float mu[4], sc[4], bt[4];
    #pragma unroll
    for (int q = 0; q < 4; q++) {
        int c = lane * 4 + q;
        double m  = g_stats[256 + c] * (1.0 / N_NODES);
        double vv = g_stats[384 + c] * (1.0 / N_NODES) - m * m;
        mu[q] = (float)m;
        sc[q] = rsqrtf((float)vv + BN_EPS) * gamma[c];
        bt[q] = beta[c];
    }

    float acc[4] = {0.f, 0.f, 0.f, 0.f};
    int cur = -1, cnt = 0;
    for (int n = n0; n < n1; n++) {
        float4 v = __ldcs(reinterpret_cast<const float4*>(&g_hB[(size_t)n * 128 + lane * 4]));
        float y[4] = { v.x, v.y, v.z, v.w };
        float ss = 0.f;
        #pragma unroll
        for (int q = 0; q < 4; q++) {
            float val = (y[q] - mu[q]) * sc[q] + bt[q];
            val = (val >= 0.f) ? val : alpha * val;
            y[q] = val;
            ss += val * val;
        }
        #pragma unroll
        for (int o = 16; o; o >>= 1) ss += __shfl_xor_sync(0xffffffffu, ss, o);
        float inv = 1.f / fmaxf(sqrtf(ss), L2_EPS);
        int g = batch[n];
        if (g != cur) {
            if (cur >= 0) {
                #pragma unroll
                for (int q = 0; q < 4; q++) atomicAdd(&g_pool[cur * 128 + lane * 4 + q], acc[q]);
                if (lane == 0) atomicAdd(&g_gcnt[cur], cnt);
            }
            cur = g; cnt = 1;
            #pragma unroll
            for (int q = 0; q < 4; q++) acc[q] = y[q] * inv;
        } else {
            cnt++;
            #pragma unroll
            for (int q = 0; q < 4; q++) acc[q] += y[q] * inv;
        }
    }
    if (cur >= 0) {
        #pragma unroll
        for (int q = 0; q < 4; q++) atomicAdd(&g_pool[cur * 128 + lane * 4 + q], acc[q]);
        if (lane == 0) atomicAdd(&g_gcnt[cur], cnt);
    }
}

// ---------------- MLP head: one block per graph ---------------------------------
__global__ __launch_bounds__(256) void k_mlp(const float* __restrict__ fc1w, const float* __restrict__ fc1b,
                                             const float* __restrict__ fc2w, const float* __restrict__ fc2b,
                                             const float* __restrict__ ow,  const float* __restrict__ ob,
                                             float* __restrict__ out) {
    int g = blockIdx.x;
    int t = threadIdx.x;
    __shared__ float sg[128], s1[256], s2[128], red[256];
    float invc = 1.f / fmaxf((float)g_gcnt[g], 1.f);
    if (t < 128) sg[t] = g_pool[g * 128 + t] * invc;
    __syncthreads();
    float s = fc1b[t];
    #pragma unroll 8
    for (int k = 0; k < 128; k++) s += sg[k] * fc1w[k * 256 + t];
    s1[t] = fmaxf(s, 0.f);
    __syncthreads();
    if (t < 128) {
        float s2v = fc2b[t];
        #pragma unroll 8
        for (int k = 0; k < 256; k++) s2v += s1[k] * fc2w[k * 128 + t];
        s2[t] = fmaxf(s2v, 0.f);
    }
    __syncthreads();
    red[t] = (t < 128) ? s2[t] * ow[t] : 0.f;
    __syncthreads();
    for (int o = 128; o > 0; o >>= 1) {
        if (t < o) red[t] += red[t + o];
        __syncthreads();
    }
    if (t == 0) out[g] = red[0] + ob[0];
}

// =============================================================================
extern "C" void kernel_launch(void* const* d_in, const int* in_sizes, int n_in,
                              void* d_out, int out_size) {
    const float* x      = (const float*)d_in[0];
    const int*   ei     = (const int*)  d_in[1];
    const int*   etype  = (const int*)  d_in[2];
    const int*   batch  = (const int*)  d_in[3];
    const float* emb    = (const float*)d_in[4];
    const float* Wrel   = (const float*)d_in[5];
    const float* Wroot  = (const float*)d_in[6];
    const float* cbias  = (const float*)d_in[7];
    const float* gamma  = (const float*)d_in[8];
    const float* beta   = (const float*)d_in[9];
    const float* pa     = (const float*)d_in[10];
    const float* fc1w   = (const float*)d_in[11];
    const float* fc1b   = (const float*)d_in[12];
    const float* fc2w   = (const float*)d_in[13];
    const float* fc2b   = (const float*)d_in[14];
    const float* ow     = (const float*)d_in[15];
    const float* ob     = (const float*)d_in[16];
    float* out = (float*)d_out;

    const int TB = 256;
    const int GEMM_SMEM = (2*128*36 + 2*32*136 + 256) * sizeof(float);
    static bool attr_set = false;
    if (!attr_set) {
        cudaFuncSetAttribute(k_gemm_tf32, cudaFuncAttributeMaxDynamicSharedMemorySize, GEMM_SMEM);
        attr_set = true;
    }

    // ---- prep + graph structure ----
    k_prep<<<(N_NODES * 4 + TB - 1) / TB, TB>>>(x);
    k_count<<<(N_EDGES + TB - 1) / TB, TB>>>(ei, etype);
    k_scan1<<<NB_SCAN, 256>>>();
    k_scan2<<<1, 512>>>();
    k_scan3<<<(N_NODES + TB - 1) / TB, TB>>>();
    k_fill<<<(N_EDGES + TB - 1) / TB, TB>>>(ei, etype);

    // ---- weights (independent of graph) ----
    k_weights<<<(N_TYPES * WCOLS + WCOLS * 128 + TB - 1) / TB, TB>>>(emb, Wrel, Wroot, cbias);

    const int nodeWarpBlocks = (N_NODES * 32 + TB - 1) / TB;
    const int npwBlocks = ((N_NODES + 15) / 16 * 32 + TB - 1) / TB;

    // ---- layer 0 (table shortcut) ----
    k_agg0<<<nodeWarpBlocks, TB>>>();
    k_bnstats0<<<512, 128>>>();
    k_bnapply0<<<nodeWarpBlocks, TB>>>(gamma, beta, pa);

    // ---- layer 1: gather-then-GEMM (tf32, pipelined, fused stats) ----
    k_gather1<<<nodeWarpBlocks, TB>>>();
    k_gemm_tf32<<<(N_NODES + 127) / 128, 256, GEMM_SMEM>>>(cbias + 128);

    // ---- fused BN+PReLU+L2norm+pool, then MLP ----
    k_bnpool<<<npwBlocks, TB>>>(batch, gamma + 128, beta + 128, pa);
    k_mlp<<<N_GRAPHS, 256>>>(fc1w, fc1b, fc2w, fc2b, ow, ob, out);
}